// round 3
// baseline (speedup 1.0000x reference)
#include <cuda_runtime.h>

// Problem constants
#define BB 8
#define TT 4096
#define DD 1024
#define LL 16                   // chunk length (timesteps per block)
#define CC (TT / LL)            // 256 chunks
#define LANES (BB * DD)         // 8192 scalar lanes
#define VLANES (LANES / 4)      // 2048 float4 lanes
#define DV (DD / 4)             // 256 float4 per row
#define NSLAB (VLANES / 256)    // 8 slabs (== batch index)
#define FLAG_STRIDE 8           // pad flags to 32B

// Scratch (static device globals; no allocation allowed)
__device__ float4 g_A[CC * VLANES];          // chunk aggregates      (8 MB)
__device__ float4 g_P[CC * VLANES];          // inclusive prefixes    (8 MB)
__device__ int    g_flag[CC * NSLAB * FLAG_STRIDE];
__device__ float  g_hfinal_scratch[LANES];

__device__ __forceinline__ float fsig_(float v) {
    float e = __expf(-v);
    return __fdividef(1.0f, 1.0f + e);
}
__device__ __forceinline__ float fsilu_(float v) {
    float e = __expf(-v);
    return __fdividef(v, 1.0f + e);
}

// ---------------------------------------------------------------------------
// Flag reset (graph replays reuse state; flags must start at 0 every replay)
// ---------------------------------------------------------------------------
__global__ void e55_reset() {
    int i = blockIdx.x * blockDim.x + threadIdx.x;
    if (i < CC * NSLAB * FLAG_STRIDE) g_flag[i] = 0;
}

// ---------------------------------------------------------------------------
// Fused single-pass chunked scan with decoupled lookback.
// Block (c, s): chunk c, batch s, 256 threads = 256 float4 lanes (dv).
// Phase A: load x chunk once (streaming), compute local states a_t (h_in=0).
// Lookback: resolve h_in from predecessors' aggregates/prefixes.
// Phase B: h_t = a_t + lam^{t+1} * h_in;  out = h^2 * sigmoid(h).
// ---------------------------------------------------------------------------
__global__ __launch_bounds__(256, 2) void e55_fused(
    const float4* __restrict__ x,
    const float4* __restrict__ h0,
    const float*  __restrict__ loglam,
    const float4* __restrict__ bias,
    float4* __restrict__ out,
    float4* __restrict__ hfinal)
{
    const int bid = blockIdx.x;
    const int c   = bid >> 3;        // chunk index (low bids -> low c: scheduled first)
    const int s   = bid & (NSLAB - 1);
    const int dv  = threadIdx.x;     // float4 column within row
    const int bi  = s;               // batch index
    const int l   = s * 256 + dv;    // global float4 lane

    const float lam = fsig_(loglam[0]);
    float lamL = lam;                // lam^16 via 4 squarings
    lamL *= lamL; lamL *= lamL; lamL *= lamL; lamL *= lamL;

    const float4 bv = bias[dv];
    const float4* xp = x + ((bi * TT + c * LL) * DV + dv);

    // ---- Phase A: read chunk once, compute running local states in regs ----
    float4 a[LL];
    #pragma unroll
    for (int t = 0; t < LL; t++)
        a[t] = __ldcs(xp + t * DV);

    float4 sa = make_float4(0.f, 0.f, 0.f, 0.f);
    #pragma unroll
    for (int t = 0; t < LL; t++) {
        float4 xs;
        xs.x = fsilu_(a[t].x);
        xs.y = fsilu_(a[t].y);
        xs.z = fsilu_(a[t].z);
        xs.w = fsilu_(a[t].w);
        sa.x = fmaf(lam, sa.x + xs.x, bv.x);
        sa.y = fmaf(lam, sa.y + xs.y, bv.y);
        sa.z = fmaf(lam, sa.z + xs.z, bv.z);
        sa.w = fmaf(lam, sa.w + xs.w, bv.w);
        a[t] = sa;                   // a_t (prefix with zero inflow)
    }
    // sa == A_c (chunk aggregate)

    __shared__ int sh_f;
    const int fidx = (c * NSLAB + s) * FLAG_STRIDE;

    float4 hin;
    if (c == 0) {
        hin = h0[l];
    } else {
        // publish aggregate
        g_A[c * VLANES + l] = sa;
        __syncthreads();
        if (dv == 0) { __threadfence(); atomicExch(&g_flag[fidx], 1); }

        // decoupled lookback
        float4 acc = make_float4(0.f, 0.f, 0.f, 0.f);
        float mult = 1.0f;
        int p = c - 1;
        while (true) {
            if (dv == 0) {
                int f = atomicOr(&g_flag[(p * NSLAB + s) * FLAG_STRIDE], 0);
                while (f == 0) {
                    __nanosleep(40);
                    f = atomicOr(&g_flag[(p * NSLAB + s) * FLAG_STRIDE], 0);
                }
                __threadfence();
                sh_f = f;
            }
            __syncthreads();
            const int f = sh_f;
            if (f == 2) {
                float4 Pp = g_P[p * VLANES + l];
                hin.x = fmaf(mult, Pp.x, acc.x);
                hin.y = fmaf(mult, Pp.y, acc.y);
                hin.z = fmaf(mult, Pp.z, acc.z);
                hin.w = fmaf(mult, Pp.w, acc.w);
                break;
            } else {
                float4 Ap = g_A[p * VLANES + l];
                acc.x = fmaf(mult, Ap.x, acc.x);
                acc.y = fmaf(mult, Ap.y, acc.y);
                acc.z = fmaf(mult, Ap.z, acc.z);
                acc.w = fmaf(mult, Ap.w, acc.w);
                mult *= lamL;
                p--;
                if (p < 0) {
                    float4 hv = h0[l];
                    hin.x = fmaf(mult, hv.x, acc.x);
                    hin.y = fmaf(mult, hv.y, acc.y);
                    hin.z = fmaf(mult, hv.z, acc.z);
                    hin.w = fmaf(mult, hv.w, acc.w);
                    break;
                }
            }
            __syncthreads();   // protect sh_f reuse
        }
    }

    // ---- publish inclusive prefix ASAP so successors stop looking back ----
    float4 P;
    P.x = fmaf(lamL, hin.x, sa.x);
    P.y = fmaf(lamL, hin.y, sa.y);
    P.z = fmaf(lamL, hin.z, sa.z);
    P.w = fmaf(lamL, hin.w, sa.w);
    g_P[c * VLANES + l] = P;
    __syncthreads();
    if (dv == 0) { __threadfence(); atomicExch(&g_flag[fidx], 2); }

    if (c == CC - 1)
        hfinal[l] = P;

    // ---- Phase B: outputs from registers ----
    float4* op = out + ((bi * TT + c * LL) * DV + dv);
    float mulp = lam;                // lam^{t+1}
    #pragma unroll
    for (int t = 0; t < LL; t++) {
        float4 h, g;
        h.x = fmaf(mulp, hin.x, a[t].x);
        h.y = fmaf(mulp, hin.y, a[t].y);
        h.z = fmaf(mulp, hin.z, a[t].z);
        h.w = fmaf(mulp, hin.w, a[t].w);
        g.x = h.x * h.x * fsig_(h.x);
        g.y = h.y * h.y * fsig_(h.y);
        g.z = h.z * h.z * fsig_(h.z);
        g.w = h.w * h.w * fsig_(h.w);
        __stcs(op + t * DV, g);
        mulp *= lam;
    }
}

// ---------------------------------------------------------------------------
// Launch
// Inputs: x [B,T,D] f32, h0 [B,D] f32, log_lambda [1] f32, b [D] f32
// Output: output [B,T,D] then h_final [B,D] (if space), f32
// ---------------------------------------------------------------------------
extern "C" void kernel_launch(void* const* d_in, const int* in_sizes, int n_in,
                              void* d_out, int out_size)
{
    const float4* x      = (const float4*)d_in[0];
    const float4* h0     = (const float4*)d_in[1];
    const float*  loglam = (const float*)d_in[2];
    const float4* bias   = (const float4*)d_in[3];
    float* out = (float*)d_out;

    const long n_output = (long)BB * TT * DD;

    float* hfinal;
    if ((long)out_size >= n_output + LANES) {
        hfinal = out + n_output;
    } else {
        void* p = nullptr;
        cudaGetSymbolAddress(&p, g_hfinal_scratch);
        hfinal = (float*)p;
    }

    const int nflags = CC * NSLAB * FLAG_STRIDE;
    e55_reset<<<(nflags + 255) / 256, 256>>>();
    e55_fused<<<CC * NSLAB, 256>>>(x, h0, loglam, bias,
                                   (float4*)out, (float4*)hfinal);
}

// round 4
// speedup vs baseline: 1.0940x; 1.0940x over previous
#include <cuda_runtime.h>

// Problem constants
#define BB 8
#define TT 4096
#define DD 1024
#define LL 32                    // chunk length (timesteps per thread)
#define CC (TT / LL)             // 128 chunks
#define LANES (BB * DD)          // 8192 scalar lanes
#define NLB (LANES / 256)        // 32 lane-blocks per chunk
#define NWG (LANES / 32)         // 256 warp-groups of lanes
#define FS 8                     // flag stride (32 B padding)

// Scratch (static device globals; no allocation allowed)
__device__ float g_A[CC * LANES];                 // chunk aggregates   (4 MB)
__device__ float g_P[CC * LANES];                 // inclusive prefixes (4 MB)
__device__ int   g_flag[CC * NWG * FS];           // per-(chunk, warp-lane-group)
__device__ float g_hfinal_scratch[LANES];

__device__ __forceinline__ float fsig_(float v) {
    float e = __expf(-v);
    return __fdividef(1.0f, 1.0f + e);
}
__device__ __forceinline__ float fsilu_(float v) {
    float e = __expf(-v);
    return __fdividef(v, 1.0f + e);
}

// ---------------------------------------------------------------------------
// Flag reset (graph replays reuse device globals; flags must start at 0)
// ---------------------------------------------------------------------------
__global__ void e55_reset() {
    int i = blockIdx.x * blockDim.x + threadIdx.x;
    if (i < CC * NWG * FS) g_flag[i] = 0;
}

// ---------------------------------------------------------------------------
// Fused single-pass chunked scan, warp-autonomous decoupled lookback.
// Thread = one scalar lane of chunk c. Local prefixes a_t (h_in = 0) live in
// 32 registers; x is read exactly once.  h_t = a_t + lam^{t+1} * h_in.
// Per-warp flags: no __syncthreads in the whole kernel.
// ---------------------------------------------------------------------------
__global__ __launch_bounds__(256, 4) void e55_fused(
    const float* __restrict__ x,
    const float* __restrict__ h0,
    const float* __restrict__ loglam,
    const float* __restrict__ bias,
    float* __restrict__ out,
    float* __restrict__ hfinal)
{
    const int bid  = blockIdx.x;
    const int c    = bid >> 5;                // chunk (low bids scheduled first)
    const int lb   = bid & (NLB - 1);
    const int tid  = threadIdx.x;
    const int j    = lb * 256 + tid;          // scalar lane [0, LANES)
    const int bi   = j >> 10;                 // batch
    const int d    = j & (DD - 1);            // feature
    const int w    = j >> 5;                  // warp-lane-group [0, NWG)
    const int lane = tid & 31;

    const float lam = fsig_(loglam[0]);
    float lamL = lam;                          // lam^32 via 5 squarings
    lamL *= lamL; lamL *= lamL; lamL *= lamL; lamL *= lamL; lamL *= lamL;

    const float bv = bias[d];
    const float* xp = x + ((bi * TT + c * LL) * DD + d);

    // ---- Phase A: stream chunk in once, local prefix states in registers ----
    float a[LL];
    #pragma unroll
    for (int t = 0; t < LL; t++)
        a[t] = __ldcs(xp + t * DD);

    float sa = 0.0f;
    #pragma unroll
    for (int t = 0; t < LL; t++) {
        float xs = fsilu_(a[t]);
        sa = fmaf(lam, sa + xs, bv);
        a[t] = sa;                             // a_t
    }
    // sa == A_c (chunk aggregate with zero inflow)

    // ---- Lookback (per-warp, fully independent) ----
    float hin;
    if (c == 0) {
        hin = h0[j];
    } else {
        __stcg(&g_A[c * LANES + j], sa);
        __threadfence();
        __syncwarp();
        if (lane == 0)
            atomicExch(&g_flag[(c * NWG + w) * FS], 1);

        float acc = 0.0f;
        float mult = 1.0f;
        int p = c - 1;
        while (true) {
            int f = 0;
            if (lane == 0) {
                f = atomicOr(&g_flag[(p * NWG + w) * FS], 0);
                while (f == 0) {
                    __nanosleep(30);
                    f = atomicOr(&g_flag[(p * NWG + w) * FS], 0);
                }
            }
            f = __shfl_sync(0xffffffffu, f, 0);
            __threadfence();                   // acquire: order data reads after flag
            if (f == 2) {
                float Pp = __ldcg(&g_P[p * LANES + j]);
                hin = fmaf(mult, Pp, acc);
                break;
            } else {
                float Ap = __ldcg(&g_A[p * LANES + j]);
                acc = fmaf(mult, Ap, acc);
                mult *= lamL;
                if (--p < 0) {
                    hin = fmaf(mult, h0[j], acc);
                    break;
                }
            }
        }
    }

    // ---- Publish inclusive prefix so successors stop early ----
    float P = fmaf(lamL, hin, sa);
    __stcg(&g_P[c * LANES + j], P);
    __threadfence();
    __syncwarp();
    if (lane == 0)
        atomicExch(&g_flag[(c * NWG + w) * FS], 2);

    if (c == CC - 1)
        hfinal[j] = P;

    // ---- Phase B: outputs from registers, streamed out once ----
    float* op = out + ((bi * TT + c * LL) * DD + d);
    float mulp = lam;                          // lam^{t+1}
    #pragma unroll
    for (int t = 0; t < LL; t++) {
        float h = fmaf(mulp, hin, a[t]);
        float g = h * h * fsig_(h);
        __stcs(op + t * DD, g);
        mulp *= lam;
    }
}

// ---------------------------------------------------------------------------
// Launch
// Inputs: x [B,T,D] f32, h0 [B,D] f32, log_lambda [1] f32, b [D] f32
// Output: output [B,T,D] then h_final [B,D] (if space), f32
// ---------------------------------------------------------------------------
extern "C" void kernel_launch(void* const* d_in, const int* in_sizes, int n_in,
                              void* d_out, int out_size)
{
    const float* x      = (const float*)d_in[0];
    const float* h0     = (const float*)d_in[1];
    const float* loglam = (const float*)d_in[2];
    const float* bias   = (const float*)d_in[3];
    float* out = (float*)d_out;

    const long n_output = (long)BB * TT * DD;

    float* hfinal;
    if ((long)out_size >= n_output + LANES) {
        hfinal = out + n_output;
    } else {
        void* p = nullptr;
        cudaGetSymbolAddress(&p, g_hfinal_scratch);
        hfinal = (float*)p;
    }

    const int nflags = CC * NWG * FS;
    e55_reset<<<(nflags + 255) / 256, 256>>>();
    e55_fused<<<CC * NLB, 256>>>(x, h0, loglam, bias, out, hfinal);
}

// round 5
// speedup vs baseline: 1.8360x; 1.6782x over previous
#include <cuda_runtime.h>

// Problem constants
#define BB 8
#define TT 4096
#define DD 1024
#define LL 128                   // output timesteps per block
#define CC (TT / LL)             // 32 chunks
#define LANES (BB * DD)          // 8192 scalar lanes
#define NLB (LANES / 256)        // 32 lane-blocks

__device__ float g_hfinal_scratch[LANES];

__device__ __forceinline__ float fsig_(float v) {
    float e = __expf(-v);
    return __fdividef(1.0f, 1.0f + e);
}
__device__ __forceinline__ float fsilu_(float v) {
    float e = __expf(-v);
    return __fdividef(v, 1.0f + e);
}

// ---------------------------------------------------------------------------
// Warmup-based chunked recurrence.
//   h_t = lam * (silu(x_t) + h_{t-1}) + b
// Influence of state W steps back is lam^W. We start each chunk from h=0 at
// t0-W with W chosen so lam^W < 2^-33 (adaptive, clamped to t0 => exact
// fallback as lam->1). For the c==0-reaching warmup, start from h0 exactly.
// No inter-block communication; x read ~1.25x, out written once.
// ---------------------------------------------------------------------------
__global__ __launch_bounds__(256) void e55_warm(
    const float* __restrict__ x,
    const float* __restrict__ h0,
    const float* __restrict__ loglam,
    const float* __restrict__ bias,
    float* __restrict__ out,
    float* __restrict__ hfinal)
{
    const int bid = blockIdx.x;
    const int c   = bid >> 5;                 // chunk index [0, CC)
    const int lb  = bid & (NLB - 1);
    const int j   = lb * 256 + threadIdx.x;   // scalar lane [0, LANES)
    const int bi  = j >> 10;                  // batch
    const int d   = j & (DD - 1);             // feature

    const float lam = fsig_(loglam[0]);

    // Required warmup depth: lam^W < 2^-33  =>  W = ceil(33*ln2 / -ln(lam))
    const int t0 = c * LL;
    int W;
    if (lam > 0.999f || lam <= 0.0f) {
        W = t0;                                // exact fallback
    } else {
        float wf = ceilf(__fdividef(22.8739f, -__logf(lam)));  // 33*ln2
        W = (wf >= (float)t0) ? t0 : (int)wf;
    }
    const int ts = t0 - W;

    const float bv = bias[d];
    float h = (ts == 0) ? h0[j] : 0.0f;

    // ---- Warmup: recurrence only, no stores ----
    const float* xp = x + ((bi * TT + ts) * DD + d);
    #pragma unroll 4
    for (int t = 0; t < W; t++) {
        float xv = xp[t * DD];
        h = fmaf(lam, h + fsilu_(xv), bv);
    }

    // ---- Main: recurrence + self-gated output ----
    const float* xm = x + ((bi * TT + t0) * DD + d);
    float*       op = out + ((bi * TT + t0) * DD + d);

    #pragma unroll 1
    for (int tb = 0; tb < LL; tb += 8) {
        float xv[8];
        #pragma unroll
        for (int k = 0; k < 8; k++)
            xv[k] = __ldcs(xm + (tb + k) * DD);
        #pragma unroll
        for (int k = 0; k < 8; k++) {
            h = fmaf(lam, h + fsilu_(xv[k]), bv);
            float g = h * h * fsig_(h);
            __stcs(op + (tb + k) * DD, g);
        }
    }

    if (c == CC - 1)
        hfinal[j] = h;
}

// ---------------------------------------------------------------------------
// Launch
// Inputs: x [B,T,D] f32, h0 [B,D] f32, log_lambda [1] f32, b [D] f32
// Output: output [B,T,D] then h_final [B,D] (if space), f32
// ---------------------------------------------------------------------------
extern "C" void kernel_launch(void* const* d_in, const int* in_sizes, int n_in,
                              void* d_out, int out_size)
{
    const float* x      = (const float*)d_in[0];
    const float* h0     = (const float*)d_in[1];
    const float* loglam = (const float*)d_in[2];
    const float* bias   = (const float*)d_in[3];
    float* out = (float*)d_out;

    const long n_output = (long)BB * TT * DD;

    float* hfinal;
    if ((long)out_size >= n_output + LANES) {
        hfinal = out + n_output;
    } else {
        void* p = nullptr;
        cudaGetSymbolAddress(&p, g_hfinal_scratch);
        hfinal = (float*)p;
    }

    e55_warm<<<CC * NLB, 256>>>(x, h0, loglam, bias, out, hfinal);
}